// round 1
// baseline (speedup 1.0000x reference)
#include <cuda_runtime.h>
#include <math.h>

#define NMAX 50000
#define EMAX 800000
#define GSEG 64

// ---------------- scratch (device globals; no allocation allowed) ----------------
__device__ float g_h[NMAX * 128];      // GAT-transformed features
__device__ float g_asrc[NMAX * 4];     // per-node attention logits (src part)
__device__ float g_adst[NMAX * 4];     // per-node attention logits (dst part)
__device__ float g_s[NMAX * 4];        // softmax denominators per dst node per head
__device__ float g_deg[NMAX];          // in-degree (incl self loop), later dinv
__device__ float g_out1[NMAX * 128];   // GAT output
__device__ float g_h2[NMAX * 128];     // out1 @ W_gcn
__device__ float g_out2[NMAX * 128];   // GCN output
__device__ float g_eg[NMAX];           // exp(gate) per node
__device__ float g_pool[GSEG];         // pooling softmax denominators
__device__ float g_rep[GSEG * 128];    // graph representations

// ---------------- zero init ----------------
__global__ void k_zero(int N) {
    long long i = (long long)blockIdx.x * blockDim.x + threadIdx.x;
    long long stride = (long long)gridDim.x * blockDim.x;
    long long n128 = (long long)N * 128;
    for (long long j = i; j < n128; j += stride) { g_out1[j] = 0.f; g_out2[j] = 0.f; }
    for (long long j = i; j < (long long)N * 4; j += stride) g_s[j] = 0.f;
    for (long long j = i; j < N; j += stride) g_deg[j] = 0.f;
    for (long long j = i; j < GSEG * 128; j += stride) g_rep[j] = 0.f;
    if (i < GSEG) g_pool[i] = 0.f;
}

// ---------------- GEMM: C[N,128] = A[N,128] @ B[128,128], fp32 ----------------
// Block tile 128 rows x 128 cols, 256 threads, each thread 8x8 outputs (strided by 16).
__global__ void gemm128(const float* __restrict__ A, const float* __restrict__ B,
                        float* __restrict__ C, int nrows) {
    __shared__ float As[8][128];  // [k][row]
    __shared__ float Bs[8][128];  // [k][col]
    int tid = threadIdx.x;
    int ty = tid >> 4;            // 0..15
    int tx = tid & 15;            // 0..15
    int row0 = blockIdx.x * 128;

    float acc[8][8];
#pragma unroll
    for (int i = 0; i < 8; i++)
#pragma unroll
        for (int j = 0; j < 8; j++) acc[i][j] = 0.f;

    for (int k0 = 0; k0 < 128; k0 += 8) {
        // load A tile transposed: each thread one float4
        int ar = tid >> 1;
        int ac = (tid & 1) * 4;
        float4 av = make_float4(0.f, 0.f, 0.f, 0.f);
        int grow = row0 + ar;
        if (grow < nrows) av = *(const float4*)(A + (long long)grow * 128 + k0 + ac);
        As[ac + 0][ar] = av.x; As[ac + 1][ar] = av.y;
        As[ac + 2][ar] = av.z; As[ac + 3][ar] = av.w;
        // load B tile: each thread one float4
        int bk = tid >> 5;
        int bc = (tid & 31) * 4;
        *(float4*)(&Bs[bk][bc]) = *(const float4*)(B + (k0 + bk) * 128 + bc);
        __syncthreads();
#pragma unroll
        for (int kk = 0; kk < 8; kk++) {
            float a[8], b[8];
#pragma unroll
            for (int i = 0; i < 8; i++) a[i] = As[kk][ty + 16 * i];
#pragma unroll
            for (int j = 0; j < 8; j++) b[j] = Bs[kk][tx + 16 * j];
#pragma unroll
            for (int i = 0; i < 8; i++)
#pragma unroll
                for (int j = 0; j < 8; j++) acc[i][j] += a[i] * b[j];
        }
        __syncthreads();
    }
#pragma unroll
    for (int i = 0; i < 8; i++) {
        int r = row0 + ty + 16 * i;
        if (r < nrows) {
#pragma unroll
            for (int j = 0; j < 8; j++)
                C[(long long)r * 128 + tx + 16 * j] = acc[i][j];
        }
    }
}

// ---------------- attention logits per node/head ----------------
__global__ void k_attn(const float* __restrict__ att_src,
                       const float* __restrict__ att_dst, int N) {
    int t = blockIdx.x * blockDim.x + threadIdx.x;
    if (t >= N * 4) return;
    int n = t >> 2, hd = t & 3;
    const float* hp = g_h + (long long)n * 128 + hd * 32;
    float s1 = 0.f, s2 = 0.f;
#pragma unroll
    for (int c = 0; c < 32; c += 4) {
        float4 hv = *(const float4*)(hp + c);
        float4 as = *(const float4*)(att_src + hd * 32 + c);
        float4 ad = *(const float4*)(att_dst + hd * 32 + c);
        s1 += hv.x * as.x + hv.y * as.y + hv.z * as.z + hv.w * as.w;
        s2 += hv.x * ad.x + hv.y * ad.y + hv.z * ad.z + hv.w * ad.w;
    }
    g_asrc[t] = s1;
    g_adst[t] = s2;
}

__device__ __forceinline__ float lrelu(float v) { return fmaxf(v, 0.2f * v); }

// ---------------- edge pass A: softmax denominators + degree ----------------
__global__ void k_edge_a(const int* __restrict__ ei, int E, int N) {
    int i = blockIdx.x * blockDim.x + threadIdx.x;
    if (i >= E + N) return;
    int s, d;
    if (i < E) { s = ei[i]; d = ei[E + i]; }
    else { s = d = i - E; }
    float4 as = *(const float4*)(g_asrc + s * 4);
    float4 ad = *(const float4*)(g_adst + d * 4);
    float e0 = expf(lrelu(as.x + ad.x));
    float e1 = expf(lrelu(as.y + ad.y));
    float e2 = expf(lrelu(as.z + ad.z));
    float e3 = expf(lrelu(as.w + ad.w));
    atomicAdd(g_s + d * 4 + 0, e0);
    atomicAdd(g_s + d * 4 + 1, e1);
    atomicAdd(g_s + d * 4 + 2, e2);
    atomicAdd(g_s + d * 4 + 3, e3);
    atomicAdd(g_deg + d, 1.0f);
}

// ---------------- edge pass B: GAT weighted aggregation (warp per edge) ----------------
__global__ void k_edge_b(const int* __restrict__ ei, int E, int N) {
    int g = blockIdx.x * blockDim.x + threadIdx.x;
    int wid = g >> 5, lane = g & 31;
    if (wid >= E + N) return;
    int s, d;
    if (wid < E) { s = ei[wid]; d = ei[E + wid]; }
    else { s = d = wid - E; }
    int head = lane >> 3;
    float a = g_asrc[s * 4 + head] + g_adst[d * 4 + head];
    float alpha = expf(lrelu(a)) / (g_s[d * 4 + head] + 1e-16f);
    float4 hv = *(const float4*)(g_h + (long long)s * 128 + lane * 4);
    float* dst = g_out1 + (long long)d * 128 + lane * 4;
    atomicAdd(dst + 0, hv.x * alpha);
    atomicAdd(dst + 1, hv.y * alpha);
    atomicAdd(dst + 2, hv.z * alpha);
    atomicAdd(dst + 3, hv.w * alpha);
}

// ---------------- post GAT: bias + elu + bn1 ----------------
__global__ void k_post1(const float* __restrict__ b_gat,
                        const float* __restrict__ bn_w,
                        const float* __restrict__ bn_b, int N) {
    int t = blockIdx.x * blockDim.x + threadIdx.x;
    if (t >= N * 32) return;
    int n = t >> 5, c4 = (t & 31) * 4;
    float4 v = *(float4*)(g_out1 + (long long)n * 128 + c4);
    float4 bg = *(const float4*)(b_gat + c4);
    float4 w = *(const float4*)(bn_w + c4);
    float4 b = *(const float4*)(bn_b + c4);
    v.x += bg.x; v.y += bg.y; v.z += bg.z; v.w += bg.w;
    v.x = v.x > 0.f ? v.x : expm1f(v.x);
    v.y = v.y > 0.f ? v.y : expm1f(v.y);
    v.z = v.z > 0.f ? v.z : expm1f(v.z);
    v.w = v.w > 0.f ? v.w : expm1f(v.w);
    v.x = v.x * w.x + b.x; v.y = v.y * w.y + b.y;
    v.z = v.z * w.z + b.z; v.w = v.w * w.w + b.w;
    *(float4*)(g_out1 + (long long)n * 128 + c4) = v;
}

// ---------------- dinv = rsqrt(max(deg,1)) in place ----------------
__global__ void k_dinv(int N) {
    int i = blockIdx.x * blockDim.x + threadIdx.x;
    if (i >= N) return;
    g_deg[i] = rsqrtf(fmaxf(g_deg[i], 1.0f));
}

// ---------------- edge pass C: GCN aggregation (warp per edge) ----------------
__global__ void k_edge_c(const int* __restrict__ ei, int E, int N) {
    int g = blockIdx.x * blockDim.x + threadIdx.x;
    int wid = g >> 5, lane = g & 31;
    if (wid >= E + N) return;
    int s, d;
    if (wid < E) { s = ei[wid]; d = ei[E + wid]; }
    else { s = d = wid - E; }
    float norm = g_deg[s] * g_deg[d];  // g_deg now holds dinv
    float4 hv = *(const float4*)(g_h2 + (long long)s * 128 + lane * 4);
    float* dst = g_out2 + (long long)d * 128 + lane * 4;
    atomicAdd(dst + 0, hv.x * norm);
    atomicAdd(dst + 1, hv.y * norm);
    atomicAdd(dst + 2, hv.z * norm);
    atomicAdd(dst + 3, hv.w * norm);
}

// ---------------- post GCN: bias + elu + bn2, gate logit + pooling denom ----------------
__global__ void k_post2_gate(const float* __restrict__ b_gcn,
                             const float* __restrict__ bn_w,
                             const float* __restrict__ bn_b,
                             const float* __restrict__ W_gate,
                             const float* __restrict__ b_gate,
                             const int* __restrict__ batch, int N) {
    int g = blockIdx.x * blockDim.x + threadIdx.x;
    int n = g >> 5, lane = g & 31;
    if (n >= N) return;
    int c4 = lane * 4;
    float4 v = *(float4*)(g_out2 + (long long)n * 128 + c4);
    float4 bg = *(const float4*)(b_gcn + c4);
    float4 w = *(const float4*)(bn_w + c4);
    float4 b = *(const float4*)(bn_b + c4);
    v.x += bg.x; v.y += bg.y; v.z += bg.z; v.w += bg.w;
    v.x = v.x > 0.f ? v.x : expm1f(v.x);
    v.y = v.y > 0.f ? v.y : expm1f(v.y);
    v.z = v.z > 0.f ? v.z : expm1f(v.z);
    v.w = v.w > 0.f ? v.w : expm1f(v.w);
    v.x = v.x * w.x + b.x; v.y = v.y * w.y + b.y;
    v.z = v.z * w.z + b.z; v.w = v.w * w.w + b.w;
    *(float4*)(g_out2 + (long long)n * 128 + c4) = v;
    // gate = out2 . W_gate + b_gate (warp reduction)
    float4 wg = *(const float4*)(W_gate + c4);
    float p = v.x * wg.x + v.y * wg.y + v.z * wg.z + v.w * wg.w;
#pragma unroll
    for (int o = 16; o; o >>= 1) p += __shfl_xor_sync(0xffffffffu, p, o);
    if (lane == 0) {
        float eg = expf(p + b_gate[0]);
        g_eg[n] = eg;
        atomicAdd(g_pool + batch[n], eg);
    }
}

// ---------------- pooling: rep[g] += (exp(gate)/Z) * out2 ----------------
__global__ void k_pool(const int* __restrict__ batch, int N) {
    int g = blockIdx.x * blockDim.x + threadIdx.x;
    int n = g >> 5, lane = g & 31;
    if (n >= N) return;
    int seg = batch[n];
    float w = g_eg[n] / (g_pool[seg] + 1e-16f);
    float4 v = *(const float4*)(g_out2 + (long long)n * 128 + lane * 4);
    float* dst = g_rep + seg * 128 + lane * 4;
    atomicAdd(dst + 0, v.x * w);
    atomicAdd(dst + 1, v.y * w);
    atomicAdd(dst + 2, v.z * w);
    atomicAdd(dst + 3, v.w * w);
}

// ---------------- final FC: out[g] = rep[g] . W_fc + b_fc ----------------
__global__ void k_final(const float* __restrict__ W_fc,
                        const float* __restrict__ b_fc, float* __restrict__ out) {
    int gph = blockIdx.x;
    int t = threadIdx.x;  // 128
    float p = g_rep[gph * 128 + t] * W_fc[t];
#pragma unroll
    for (int o = 16; o; o >>= 1) p += __shfl_xor_sync(0xffffffffu, p, o);
    __shared__ float red[4];
    if ((t & 31) == 0) red[t >> 5] = p;
    __syncthreads();
    if (t == 0) out[gph] = red[0] + red[1] + red[2] + red[3] + b_fc[0];
}

extern "C" void kernel_launch(void* const* d_in, const int* in_sizes, int n_in,
                              void* d_out, int out_size) {
    const float* x       = (const float*)d_in[0];
    const int*   ei      = (const int*)d_in[1];
    const int*   batch   = (const int*)d_in[2];
    const float* W_gat   = (const float*)d_in[3];
    const float* att_src = (const float*)d_in[4];
    const float* att_dst = (const float*)d_in[5];
    const float* b_gat   = (const float*)d_in[6];
    const float* bn1_w   = (const float*)d_in[7];
    const float* bn1_b   = (const float*)d_in[8];
    const float* W_gcn   = (const float*)d_in[9];
    const float* b_gcn   = (const float*)d_in[10];
    const float* bn2_w   = (const float*)d_in[11];
    const float* bn2_b   = (const float*)d_in[12];
    const float* W_gate  = (const float*)d_in[13];
    const float* b_gate  = (const float*)d_in[14];
    const float* W_fc    = (const float*)d_in[15];
    const float* b_fc    = (const float*)d_in[16];
    float* out = (float*)d_out;

    int N = in_sizes[0] / 128;
    int E = in_sizes[1] / 2;
    if (N > NMAX) N = NMAX;
    if (E > EMAX) E = EMAX;

    float *p_h, *p_out1, *p_h2;
    cudaGetSymbolAddress((void**)&p_h, g_h);
    cudaGetSymbolAddress((void**)&p_out1, g_out1);
    cudaGetSymbolAddress((void**)&p_h2, g_h2);

    int EP = E + N;  // edges incl. self loops

    k_zero<<<8192, 256>>>(N);
    gemm128<<<(N + 127) / 128, 256>>>(x, W_gat, p_h, N);
    k_attn<<<(N * 4 + 255) / 256, 256>>>(att_src, att_dst, N);
    k_edge_a<<<(EP + 255) / 256, 256>>>(ei, E, N);
    k_edge_b<<<(EP * 32 + 255) / 256, 256>>>(ei, E, N);
    k_post1<<<(N * 32 + 255) / 256, 256>>>(b_gat, bn1_w, bn1_b, N);
    k_dinv<<<(N + 255) / 256, 256>>>(N);
    gemm128<<<(N + 127) / 128, 256>>>(p_out1, W_gcn, p_h2, N);
    k_edge_c<<<(EP * 32 + 255) / 256, 256>>>(ei, E, N);
    k_post2_gate<<<(N * 32 + 255) / 256, 256>>>(b_gcn, bn2_w, bn2_b, W_gate, b_gate, batch, N);
    k_pool<<<(N * 32 + 255) / 256, 256>>>(batch, N);
    k_final<<<64, 128>>>(W_fc, b_fc, out);
}

// round 2
// speedup vs baseline: 2.1513x; 2.1513x over previous
#include <cuda_runtime.h>
#include <math.h>

#define NMAX 50000
#define EMAX 800000
#define GSEG 64

// ---------------- scratch (device globals; no allocation allowed) ----------------
__device__ float g_h[NMAX * 128];      // GAT-transformed features
__device__ float g_asrc[NMAX * 4];     // per-node attention logits (src part)
__device__ float g_adst[NMAX * 4];     // per-node attention logits (dst part)
__device__ float g_out1[NMAX * 128];   // GAT output
__device__ float g_h2[NMAX * 128];     // out1 @ W_gcn
__device__ float g_out2[NMAX * 128];   // GCN output
__device__ float g_dinv[NMAX];         // 1/sqrt(deg)
__device__ float g_eg[NMAX];           // exp(gate) per node
__device__ int   g_deg[NMAX];          // degree counts (incl self loop)
__device__ int   g_rowptr[NMAX + 1];   // CSR row pointers (by dst)
__device__ int   g_wpos[NMAX];         // fill cursors
__device__ int   g_col[EMAX + NMAX];   // CSR column (src node ids)
__device__ int   g_segstart[GSEG + 1]; // graph segment boundaries (batch is sorted)

__device__ __forceinline__ float lrelu(float v) { return fmaxf(v, 0.2f * v); }

// ---------------- CSR build ----------------
__global__ void k_init(int N) {
    int i = blockIdx.x * blockDim.x + threadIdx.x;
    if (i < N) g_deg[i] = 1;  // self loop
}

__global__ void k_count(const int* __restrict__ ei, int E) {
    int i = blockIdx.x * blockDim.x + threadIdx.x;
    if (i < E) atomicAdd(&g_deg[ei[E + i]], 1);
}

__global__ void k_scan(int N) {
    __shared__ int part[1024];
    int tid = threadIdx.x;
    int chunk = (N + 1023) >> 10;
    int s0 = tid * chunk, e0 = min(s0 + chunk, N);
    int s = 0;
    for (int i = s0; i < e0; i++) s += g_deg[i];
    part[tid] = s;
    __syncthreads();
    for (int off = 1; off < 1024; off <<= 1) {
        int v = (tid >= off) ? part[tid - off] : 0;
        __syncthreads();
        part[tid] += v;
        __syncthreads();
    }
    int base = (tid == 0) ? 0 : part[tid - 1];
    for (int i = s0; i < e0; i++) {
        int d = g_deg[i];
        g_rowptr[i] = base;
        g_wpos[i] = base;
        base += d;
    }
    if (tid == 1023) g_rowptr[N] = part[1023];
}

__global__ void k_fill(const int* __restrict__ ei, int E, int N) {
    int i = blockIdx.x * blockDim.x + threadIdx.x;
    if (i >= E + N) return;
    int s, d;
    if (i < E) { s = ei[i]; d = ei[E + i]; }
    else { s = d = i - E; }
    int pos = atomicAdd(&g_wpos[d], 1);
    g_col[pos] = s;
}

__global__ void k_dinv(int N) {
    int i = blockIdx.x * blockDim.x + threadIdx.x;
    if (i < N) g_dinv[i] = rsqrtf((float)(g_rowptr[i + 1] - g_rowptr[i]));
}

// ---------------- GEMM: C[N,128] = A[N,128] @ B[128,128], fp32 ----------------
__global__ void gemm128(const float* __restrict__ A, const float* __restrict__ B,
                        float* __restrict__ C, int nrows) {
    __shared__ float As[8][128];
    __shared__ float Bs[8][128];
    int tid = threadIdx.x;
    int ty = tid >> 4;
    int tx = tid & 15;
    int row0 = blockIdx.x * 128;

    float acc[8][8];
#pragma unroll
    for (int i = 0; i < 8; i++)
#pragma unroll
        for (int j = 0; j < 8; j++) acc[i][j] = 0.f;

    for (int k0 = 0; k0 < 128; k0 += 8) {
        int ar = tid >> 1;
        int ac = (tid & 1) * 4;
        float4 av = make_float4(0.f, 0.f, 0.f, 0.f);
        int grow = row0 + ar;
        if (grow < nrows) av = *(const float4*)(A + (long long)grow * 128 + k0 + ac);
        As[ac + 0][ar] = av.x; As[ac + 1][ar] = av.y;
        As[ac + 2][ar] = av.z; As[ac + 3][ar] = av.w;
        int bk = tid >> 5;
        int bc = (tid & 31) * 4;
        *(float4*)(&Bs[bk][bc]) = *(const float4*)(B + (k0 + bk) * 128 + bc);
        __syncthreads();
#pragma unroll
        for (int kk = 0; kk < 8; kk++) {
            float a[8], b[8];
#pragma unroll
            for (int i = 0; i < 8; i++) a[i] = As[kk][ty + 16 * i];
#pragma unroll
            for (int j = 0; j < 8; j++) b[j] = Bs[kk][tx + 16 * j];
#pragma unroll
            for (int i = 0; i < 8; i++)
#pragma unroll
                for (int j = 0; j < 8; j++) acc[i][j] += a[i] * b[j];
        }
        __syncthreads();
    }
#pragma unroll
    for (int i = 0; i < 8; i++) {
        int r = row0 + ty + 16 * i;
        if (r < nrows) {
#pragma unroll
            for (int j = 0; j < 8; j++)
                C[(long long)r * 128 + tx + 16 * j] = acc[i][j];
        }
    }
}

// ---------------- attention logits per node/head ----------------
__global__ void k_attn(const float* __restrict__ att_src,
                       const float* __restrict__ att_dst, int N) {
    int t = blockIdx.x * blockDim.x + threadIdx.x;
    if (t >= N * 4) return;
    int n = t >> 2, hd = t & 3;
    const float* hp = g_h + (long long)n * 128 + hd * 32;
    float s1 = 0.f, s2 = 0.f;
#pragma unroll
    for (int c = 0; c < 32; c += 4) {
        float4 hv = *(const float4*)(hp + c);
        float4 as = *(const float4*)(att_src + hd * 32 + c);
        float4 ad = *(const float4*)(att_dst + hd * 32 + c);
        s1 += hv.x * as.x + hv.y * as.y + hv.z * as.z + hv.w * as.w;
        s2 += hv.x * ad.x + hv.y * ad.y + hv.z * ad.z + hv.w * ad.w;
    }
    g_asrc[t] = s1;
    g_adst[t] = s2;
}

// ---------------- GAT aggregation (warp per dst node, gather) ----------------
__global__ void k_gat_agg(const float* __restrict__ b_gat,
                          const float* __restrict__ bn_w,
                          const float* __restrict__ bn_b, int N) {
    __shared__ int   s_col[8][32];
    __shared__ float s_w[8][128];
    int t = blockIdx.x * blockDim.x + threadIdx.x;
    int node = t >> 5, lane = t & 31;
    int w = threadIdx.x >> 5;
    if (node >= N) return;
    int beg = g_rowptr[node], end = g_rowptr[node + 1];
    float4 ad = *(const float4*)(g_adst + node * 4);

    // phase 1: softmax denominators (lane-parallel over edges)
    float4 ssum = make_float4(0.f, 0.f, 0.f, 0.f);
    for (int i = beg + lane; i < end; i += 32) {
        int s = g_col[i];
        float4 as = *(const float4*)(g_asrc + s * 4);
        ssum.x += expf(lrelu(as.x + ad.x));
        ssum.y += expf(lrelu(as.y + ad.y));
        ssum.z += expf(lrelu(as.z + ad.z));
        ssum.w += expf(lrelu(as.w + ad.w));
    }
#pragma unroll
    for (int o = 16; o; o >>= 1) {
        ssum.x += __shfl_xor_sync(0xffffffffu, ssum.x, o);
        ssum.y += __shfl_xor_sync(0xffffffffu, ssum.y, o);
        ssum.z += __shfl_xor_sync(0xffffffffu, ssum.z, o);
        ssum.w += __shfl_xor_sync(0xffffffffu, ssum.w, o);
    }
    float4 inv;
    inv.x = 1.f / (ssum.x + 1e-16f);
    inv.y = 1.f / (ssum.y + 1e-16f);
    inv.z = 1.f / (ssum.z + 1e-16f);
    inv.w = 1.f / (ssum.w + 1e-16f);

    int head = lane >> 3;
    float4 acc = make_float4(0.f, 0.f, 0.f, 0.f);
    for (int cb = beg; cb < end; cb += 32) {
        int m = min(32, end - cb);
        if (lane < m) {
            int s = g_col[cb + lane];
            float4 as = *(const float4*)(g_asrc + s * 4);
            s_col[w][lane] = s;
            s_w[w][lane * 4 + 0] = expf(lrelu(as.x + ad.x)) * inv.x;
            s_w[w][lane * 4 + 1] = expf(lrelu(as.y + ad.y)) * inv.y;
            s_w[w][lane * 4 + 2] = expf(lrelu(as.z + ad.z)) * inv.z;
            s_w[w][lane * 4 + 3] = expf(lrelu(as.w + ad.w)) * inv.w;
        }
        __syncwarp();
#pragma unroll 4
        for (int j = 0; j < m; j++) {
            int s = s_col[w][j];
            float ww = s_w[w][j * 4 + head];
            float4 hv = *(const float4*)(g_h + (long long)s * 128 + lane * 4);
            acc.x += ww * hv.x; acc.y += ww * hv.y;
            acc.z += ww * hv.z; acc.w += ww * hv.w;
        }
        __syncwarp();
    }
    // epilogue: bias + elu + bn1
    int c4 = lane * 4;
    float4 bg = *(const float4*)(b_gat + c4);
    float4 wv = *(const float4*)(bn_w + c4);
    float4 bv = *(const float4*)(bn_b + c4);
    acc.x += bg.x; acc.y += bg.y; acc.z += bg.z; acc.w += bg.w;
    acc.x = acc.x > 0.f ? acc.x : expm1f(acc.x);
    acc.y = acc.y > 0.f ? acc.y : expm1f(acc.y);
    acc.z = acc.z > 0.f ? acc.z : expm1f(acc.z);
    acc.w = acc.w > 0.f ? acc.w : expm1f(acc.w);
    acc.x = acc.x * wv.x + bv.x; acc.y = acc.y * wv.y + bv.y;
    acc.z = acc.z * wv.z + bv.z; acc.w = acc.w * wv.w + bv.w;
    *(float4*)(g_out1 + (long long)node * 128 + c4) = acc;
}

// ---------------- GCN aggregation (warp per dst node) + post + gate ----------------
__global__ void k_gcn_agg(const float* __restrict__ b_gcn,
                          const float* __restrict__ bn_w,
                          const float* __restrict__ bn_b,
                          const float* __restrict__ W_gate,
                          const float* __restrict__ b_gate, int N) {
    __shared__ int   s_col[8][32];
    __shared__ float s_dv[8][32];
    int t = blockIdx.x * blockDim.x + threadIdx.x;
    int node = t >> 5, lane = t & 31;
    int w = threadIdx.x >> 5;
    if (node >= N) return;
    int beg = g_rowptr[node], end = g_rowptr[node + 1];

    float4 acc = make_float4(0.f, 0.f, 0.f, 0.f);
    for (int cb = beg; cb < end; cb += 32) {
        int m = min(32, end - cb);
        if (lane < m) {
            int s = g_col[cb + lane];
            s_col[w][lane] = s;
            s_dv[w][lane] = g_dinv[s];
        }
        __syncwarp();
#pragma unroll 4
        for (int j = 0; j < m; j++) {
            int s = s_col[w][j];
            float dv = s_dv[w][j];
            float4 hv = *(const float4*)(g_h2 + (long long)s * 128 + lane * 4);
            acc.x += dv * hv.x; acc.y += dv * hv.y;
            acc.z += dv * hv.z; acc.w += dv * hv.w;
        }
        __syncwarp();
    }
    float dd = g_dinv[node];
    acc.x *= dd; acc.y *= dd; acc.z *= dd; acc.w *= dd;

    int c4 = lane * 4;
    float4 bg = *(const float4*)(b_gcn + c4);
    float4 wv = *(const float4*)(bn_w + c4);
    float4 bv = *(const float4*)(bn_b + c4);
    acc.x += bg.x; acc.y += bg.y; acc.z += bg.z; acc.w += bg.w;
    acc.x = acc.x > 0.f ? acc.x : expm1f(acc.x);
    acc.y = acc.y > 0.f ? acc.y : expm1f(acc.y);
    acc.z = acc.z > 0.f ? acc.z : expm1f(acc.z);
    acc.w = acc.w > 0.f ? acc.w : expm1f(acc.w);
    acc.x = acc.x * wv.x + bv.x; acc.y = acc.y * wv.y + bv.y;
    acc.z = acc.z * wv.z + bv.z; acc.w = acc.w * wv.w + bv.w;
    *(float4*)(g_out2 + (long long)node * 128 + c4) = acc;

    // gate logit + exp
    float4 wg = *(const float4*)(W_gate + c4);
    float p = acc.x * wg.x + acc.y * wg.y + acc.z * wg.z + acc.w * wg.w;
#pragma unroll
    for (int o = 16; o; o >>= 1) p += __shfl_xor_sync(0xffffffffu, p, o);
    if (lane == 0) g_eg[node] = expf(p + b_gate[0]);
}

// ---------------- segment boundaries (batch is sorted ascending) ----------------
__global__ void k_bounds(const int* __restrict__ batch, int N) {
    int n = blockIdx.x * blockDim.x + threadIdx.x;
    if (n >= N) return;
    int b = batch[n];
    int pb = (n == 0) ? -1 : batch[n - 1];
    for (int g = pb + 1; g <= b; g++) g_segstart[g] = n;
    if (n == N - 1)
        for (int g = b + 1; g <= GSEG; g++) g_segstart[g] = N;
}

// ---------------- pooling + final FC fused: one block per graph ----------------
__global__ void k_pool_final(const float* __restrict__ W_fc,
                             const float* __restrict__ b_fc,
                             float* __restrict__ out) {
    __shared__ float red[4];
    __shared__ float s_inv;
    int gph = blockIdx.x;
    int t = threadIdx.x;  // 128
    int lane = t & 31, wrp = t >> 5;
    int beg = g_segstart[gph], end = g_segstart[gph + 1];

    // softmax denominator over segment
    float s = 0.f;
    for (int n = beg + t; n < end; n += 128) s += g_eg[n];
#pragma unroll
    for (int o = 16; o; o >>= 1) s += __shfl_xor_sync(0xffffffffu, s, o);
    if (lane == 0) red[wrp] = s;
    __syncthreads();
    if (t == 0) s_inv = 1.f / (red[0] + red[1] + red[2] + red[3] + 1e-16f);
    __syncthreads();
    float inv = s_inv;

    // weighted feature sum: thread t owns channel t
    float acc = 0.f;
    int n = beg;
    for (; n + 4 <= end; n += 4) {
        float w0 = g_eg[n + 0] * inv;
        float w1 = g_eg[n + 1] * inv;
        float w2 = g_eg[n + 2] * inv;
        float w3 = g_eg[n + 3] * inv;
        acc += w0 * g_out2[(long long)(n + 0) * 128 + t];
        acc += w1 * g_out2[(long long)(n + 1) * 128 + t];
        acc += w2 * g_out2[(long long)(n + 2) * 128 + t];
        acc += w3 * g_out2[(long long)(n + 3) * 128 + t];
    }
    for (; n < end; n++)
        acc += (g_eg[n] * inv) * g_out2[(long long)n * 128 + t];

    // dot with W_fc
    float p = acc * W_fc[t];
#pragma unroll
    for (int o = 16; o; o >>= 1) p += __shfl_xor_sync(0xffffffffu, p, o);
    __syncthreads();
    if (lane == 0) red[wrp] = p;
    __syncthreads();
    if (t == 0) out[gph] = red[0] + red[1] + red[2] + red[3] + b_fc[0];
}

extern "C" void kernel_launch(void* const* d_in, const int* in_sizes, int n_in,
                              void* d_out, int out_size) {
    const float* x       = (const float*)d_in[0];
    const int*   ei      = (const int*)d_in[1];
    const int*   batch   = (const int*)d_in[2];
    const float* W_gat   = (const float*)d_in[3];
    const float* att_src = (const float*)d_in[4];
    const float* att_dst = (const float*)d_in[5];
    const float* b_gat   = (const float*)d_in[6];
    const float* bn1_w   = (const float*)d_in[7];
    const float* bn1_b   = (const float*)d_in[8];
    const float* W_gcn   = (const float*)d_in[9];
    const float* b_gcn   = (const float*)d_in[10];
    const float* bn2_w   = (const float*)d_in[11];
    const float* bn2_b   = (const float*)d_in[12];
    const float* W_gate  = (const float*)d_in[13];
    const float* b_gate  = (const float*)d_in[14];
    const float* W_fc    = (const float*)d_in[15];
    const float* b_fc    = (const float*)d_in[16];
    float* out = (float*)d_out;

    int N = in_sizes[0] / 128;
    int E = in_sizes[1] / 2;
    if (N > NMAX) N = NMAX;
    if (E > EMAX) E = EMAX;

    float *p_h, *p_out1, *p_h2;
    cudaGetSymbolAddress((void**)&p_h, g_h);
    cudaGetSymbolAddress((void**)&p_out1, g_out1);
    cudaGetSymbolAddress((void**)&p_h2, g_h2);

    // CSR build
    k_init<<<(N + 255) / 256, 256>>>(N);
    k_count<<<(E + 255) / 256, 256>>>(ei, E);
    k_scan<<<1, 1024>>>(N);
    k_fill<<<(E + N + 255) / 256, 256>>>(ei, E, N);
    k_dinv<<<(N + 255) / 256, 256>>>(N);

    // GAT
    gemm128<<<(N + 127) / 128, 256>>>(x, W_gat, p_h, N);
    k_attn<<<(N * 4 + 255) / 256, 256>>>(att_src, att_dst, N);
    k_gat_agg<<<(N * 32 + 255) / 256, 256>>>(b_gat, bn1_w, bn1_b, N);

    // GCN
    gemm128<<<(N + 127) / 128, 256>>>(p_out1, W_gcn, p_h2, N);
    k_gcn_agg<<<(N * 32 + 255) / 256, 256>>>(b_gcn, bn2_w, bn2_b, W_gate, b_gate, N);

    // Pooling + FC
    k_bounds<<<(N + 255) / 256, 256>>>(batch, N);
    k_pool_final<<<GSEG, 128>>>(W_fc, b_fc, out);
}

// round 3
// speedup vs baseline: 2.1860x; 1.0161x over previous
#include <cuda_runtime.h>
#include <math.h>

#define NMAX 50000
#define EMAX 800000
#define GSEG 64

// ---------------- scratch (device globals; no allocation allowed) ----------------
__device__ float g_h[NMAX * 128];      // GAT-transformed features
__device__ float g_asrc[NMAX * 4];     // per-node attention logits (src part)
__device__ float g_adst[NMAX * 4];     // per-node attention logits (dst part)
__device__ float g_out1[NMAX * 128];   // GAT output
__device__ float g_h2[NMAX * 128];     // out1 @ W_gcn
__device__ float g_out2[NMAX * 128];   // GCN output
__device__ float g_dinv[NMAX];         // 1/sqrt(deg)
__device__ float g_eg[NMAX];           // exp(gate) per node
__device__ int   g_deg[NMAX];          // degree counts (excl self loop)
__device__ int   g_rowptr[NMAX + 1];   // CSR row pointers (by dst)
__device__ int   g_wpos[NMAX];         // fill cursors
__device__ int   g_col[EMAX + NMAX];   // CSR column (src node ids)
__device__ int   g_segstart[GSEG + 1]; // graph segment boundaries (batch sorted)

__device__ __forceinline__ float lrelu(float v) { return fmaxf(v, 0.2f * v); }
__device__ __forceinline__ float elu(float v) { return v > 0.f ? v : __expf(v) - 1.f; }

// ---------------- prep: zero degrees + segment bounds ----------------
__global__ void k_prep(const int* __restrict__ batch, int N) {
    int n = blockIdx.x * blockDim.x + threadIdx.x;
    if (n >= N) return;
    g_deg[n] = 0;
    int b = batch[n];
    int pb = (n == 0) ? -1 : batch[n - 1];
    for (int g = pb + 1; g <= b; g++) g_segstart[g] = n;
    if (n == N - 1)
        for (int g = b + 1; g <= GSEG; g++) g_segstart[g] = N;
}

__global__ void k_count(const int* __restrict__ ei, int E) {
    int i = blockIdx.x * blockDim.x + threadIdx.x;
    if (i < E) atomicAdd(&g_deg[__ldg(ei + E + i)], 1);
}

// scan: rowptr (deg+1 incl self loop), self-loop placed at slot 0, dinv fused
__global__ void k_scan(int N) {
    __shared__ int part[1024];
    int tid = threadIdx.x;
    int chunk = (N + 1023) >> 10;
    int s0 = tid * chunk, e0 = min(s0 + chunk, N);
    int s = 0;
    for (int i = s0; i < e0; i++) s += g_deg[i] + 1;
    part[tid] = s;
    __syncthreads();
    for (int off = 1; off < 1024; off <<= 1) {
        int v = (tid >= off) ? part[tid - off] : 0;
        __syncthreads();
        part[tid] += v;
        __syncthreads();
    }
    int base = (tid == 0) ? 0 : part[tid - 1];
    for (int i = s0; i < e0; i++) {
        int rd = g_deg[i] + 1;
        g_rowptr[i] = base;
        g_col[base] = i;        // self loop in slot 0
        g_wpos[i] = base + 1;   // edges fill after
        g_dinv[i] = rsqrtf((float)rd);
        base += rd;
    }
    if (tid == 1023) g_rowptr[N] = part[1023];
}

__global__ void k_fill(const int* __restrict__ ei, int E) {
    int i = blockIdx.x * blockDim.x + threadIdx.x;
    if (i >= E) return;
    int s = __ldg(ei + i);
    int d = __ldg(ei + E + i);
    int pos = atomicAdd(&g_wpos[d], 1);
    g_col[pos] = s;
}

// ---------------- GEMM: C[N,128] = A[N,128] @ B[128,128], fp32 ----------------
// 128x128 tile, 256 threads, 8x8 per thread with 4-consecutive mapping (LDS.128)
__global__ void gemm128(const float* __restrict__ A, const float* __restrict__ B,
                        float* __restrict__ C, int nrows) {
    __shared__ float As[8][128];  // [k][row]
    __shared__ float Bs[8][128];  // [k][col]
    int tid = threadIdx.x;
    int ty = tid >> 4;            // 0..15
    int tx = tid & 15;            // 0..15
    int row0 = blockIdx.x * 128;

    float acc[8][8];
#pragma unroll
    for (int i = 0; i < 8; i++)
#pragma unroll
        for (int j = 0; j < 8; j++) acc[i][j] = 0.f;

    int ar = tid >> 1;
    int ac = (tid & 1) * 4;
    int bk = tid >> 5;
    int bc = (tid & 31) * 4;

    for (int k0 = 0; k0 < 128; k0 += 8) {
        float4 av = make_float4(0.f, 0.f, 0.f, 0.f);
        if (row0 + ar < nrows)
            av = *(const float4*)(A + (long long)(row0 + ar) * 128 + k0 + ac);
        float4 bv = *(const float4*)(B + (long long)(k0 + bk) * 128 + bc);
        __syncthreads();
        As[ac + 0][ar] = av.x; As[ac + 1][ar] = av.y;
        As[ac + 2][ar] = av.z; As[ac + 3][ar] = av.w;
        *(float4*)(&Bs[bk][bc]) = bv;
        __syncthreads();
#pragma unroll
        for (int kk = 0; kk < 8; kk++) {
            float4 a0 = *(const float4*)(&As[kk][ty * 4]);
            float4 a1 = *(const float4*)(&As[kk][ty * 4 + 64]);
            float4 b0 = *(const float4*)(&Bs[kk][tx * 4]);
            float4 b1 = *(const float4*)(&Bs[kk][tx * 4 + 64]);
            float a[8] = {a0.x, a0.y, a0.z, a0.w, a1.x, a1.y, a1.z, a1.w};
            float b[8] = {b0.x, b0.y, b0.z, b0.w, b1.x, b1.y, b1.z, b1.w};
#pragma unroll
            for (int i = 0; i < 8; i++)
#pragma unroll
                for (int j = 0; j < 8; j++) acc[i][j] += a[i] * b[j];
        }
    }
#pragma unroll
    for (int i = 0; i < 8; i++) {
        int r = row0 + ty * 4 + (i < 4 ? i : 60 + i);
        if (r < nrows) {
            *(float4*)(C + (long long)r * 128 + tx * 4) =
                make_float4(acc[i][0], acc[i][1], acc[i][2], acc[i][3]);
            *(float4*)(C + (long long)r * 128 + tx * 4 + 64) =
                make_float4(acc[i][4], acc[i][5], acc[i][6], acc[i][7]);
        }
    }
}

// ---------------- attention logits per node/head ----------------
__global__ void k_attn(const float* __restrict__ att_src,
                       const float* __restrict__ att_dst, int N) {
    int t = blockIdx.x * blockDim.x + threadIdx.x;
    if (t >= N * 4) return;
    int n = t >> 2, hd = t & 3;
    const float* hp = g_h + (long long)n * 128 + hd * 32;
    float s1 = 0.f, s2 = 0.f;
#pragma unroll
    for (int c = 0; c < 32; c += 4) {
        float4 hv = *(const float4*)(hp + c);
        float4 as = *(const float4*)(att_src + hd * 32 + c);
        float4 ad = *(const float4*)(att_dst + hd * 32 + c);
        s1 += hv.x * as.x + hv.y * as.y + hv.z * as.z + hv.w * as.w;
        s2 += hv.x * ad.x + hv.y * ad.y + hv.z * ad.z + hv.w * ad.w;
    }
    g_asrc[t] = s1;
    g_adst[t] = s2;
}

// ---------------- GAT aggregation: warp per dst node, single pass ----------------
// out = (sum_j e_j * h_j) / (sum_j e_j); per-lane den is already the full sum.
__global__ void k_gat_agg(const float* __restrict__ b_gat,
                          const float* __restrict__ bn_w,
                          const float* __restrict__ bn_b, int N) {
    int t = blockIdx.x * blockDim.x + threadIdx.x;
    int node = t >> 5, lane = t & 31;
    if (node >= N) return;
    int head = lane >> 3;
    int beg = g_rowptr[node], end = g_rowptr[node + 1];
    float adh = g_adst[node * 4 + head];

    float4 acc = make_float4(0.f, 0.f, 0.f, 0.f);
    float den = 0.f;
#pragma unroll 4
    for (int i = beg; i < end; i++) {
        int s = __ldg(&g_col[i]);                        // broadcast
        float a = __ldg(&g_asrc[s * 4 + head]);          // 4 addrs/warp
        float e = __expf(lrelu(a + adh));
        den += e;
        float4 hv = *(const float4*)(g_h + (long long)s * 128 + lane * 4);
        acc.x += e * hv.x; acc.y += e * hv.y;
        acc.z += e * hv.z; acc.w += e * hv.w;
    }
    float inv = 1.f / (den + 1e-16f);
    int c4 = lane * 4;
    float4 bg = *(const float4*)(b_gat + c4);
    float4 wv = *(const float4*)(bn_w + c4);
    float4 bv = *(const float4*)(bn_b + c4);
    acc.x = elu(acc.x * inv + bg.x) * wv.x + bv.x;
    acc.y = elu(acc.y * inv + bg.y) * wv.y + bv.y;
    acc.z = elu(acc.z * inv + bg.z) * wv.z + bv.z;
    acc.w = elu(acc.w * inv + bg.w) * wv.w + bv.w;
    *(float4*)(g_out1 + (long long)node * 128 + c4) = acc;
}

// ---------------- GCN aggregation + post + gate ----------------
__global__ void k_gcn_agg(const float* __restrict__ b_gcn,
                          const float* __restrict__ bn_w,
                          const float* __restrict__ bn_b,
                          const float* __restrict__ W_gate,
                          const float* __restrict__ b_gate, int N) {
    int t = blockIdx.x * blockDim.x + threadIdx.x;
    int node = t >> 5, lane = t & 31;
    if (node >= N) return;
    int beg = g_rowptr[node], end = g_rowptr[node + 1];

    float4 acc = make_float4(0.f, 0.f, 0.f, 0.f);
#pragma unroll 4
    for (int i = beg; i < end; i++) {
        int s = __ldg(&g_col[i]);             // broadcast
        float dv = __ldg(&g_dinv[s]);         // broadcast
        float4 hv = *(const float4*)(g_h2 + (long long)s * 128 + lane * 4);
        acc.x += dv * hv.x; acc.y += dv * hv.y;
        acc.z += dv * hv.z; acc.w += dv * hv.w;
    }
    float dd = g_dinv[node];
    int c4 = lane * 4;
    float4 bg = *(const float4*)(b_gcn + c4);
    float4 wv = *(const float4*)(bn_w + c4);
    float4 bv = *(const float4*)(bn_b + c4);
    acc.x = elu(acc.x * dd + bg.x) * wv.x + bv.x;
    acc.y = elu(acc.y * dd + bg.y) * wv.y + bv.y;
    acc.z = elu(acc.z * dd + bg.z) * wv.z + bv.z;
    acc.w = elu(acc.w * dd + bg.w) * wv.w + bv.w;
    *(float4*)(g_out2 + (long long)node * 128 + c4) = acc;

    // gate logit + exp
    float4 wg = *(const float4*)(W_gate + c4);
    float p = acc.x * wg.x + acc.y * wg.y + acc.z * wg.z + acc.w * wg.w;
#pragma unroll
    for (int o = 16; o; o >>= 1) p += __shfl_xor_sync(0xffffffffu, p, o);
    if (lane == 0) g_eg[node] = __expf(p + b_gate[0]);
}

// ---------------- pooling + final FC fused: one block (256 thr) per graph ----------------
__global__ void k_pool_final(const float* __restrict__ W_fc,
                             const float* __restrict__ b_fc,
                             float* __restrict__ out) {
    __shared__ float red[8];
    __shared__ float s_acc[256];
    __shared__ float s_inv;
    int gph = blockIdx.x;
    int t = threadIdx.x;  // 256
    int lane = t & 31, wrp = t >> 5;
    int beg = g_segstart[gph], end = g_segstart[gph + 1];

    // softmax denominator over segment
    float s = 0.f;
    for (int n = beg + t; n < end; n += 256) s += g_eg[n];
#pragma unroll
    for (int o = 16; o; o >>= 1) s += __shfl_xor_sync(0xffffffffu, s, o);
    if (lane == 0) red[wrp] = s;
    __syncthreads();
    if (t == 0) {
        float tot = 0.f;
#pragma unroll
        for (int i = 0; i < 8; i++) tot += red[i];
        s_inv = 1.f / (tot + 1e-16f);
    }
    __syncthreads();
    float inv = s_inv;

    // weighted feature sum: half=t>>7 picks node parity, c=t&127 channel
    int half = t >> 7, c = t & 127;
    float acc = 0.f;
    int n = beg + half;
    for (; n + 8 <= end; n += 8) {
        acc += g_eg[n + 0] * g_out2[(long long)(n + 0) * 128 + c];
        acc += g_eg[n + 2] * g_out2[(long long)(n + 2) * 128 + c];
        acc += g_eg[n + 4] * g_out2[(long long)(n + 4) * 128 + c];
        acc += g_eg[n + 6] * g_out2[(long long)(n + 6) * 128 + c];
    }
    for (; n < end; n += 2)
        acc += g_eg[n] * g_out2[(long long)n * 128 + c];
    s_acc[t] = acc;
    __syncthreads();

    if (t < 128) {
        float p = (s_acc[t] + s_acc[t + 128]) * inv * W_fc[t];
#pragma unroll
        for (int o = 16; o; o >>= 1) p += __shfl_xor_sync(0xffffffffu, p, o);
        if (lane == 0) red[wrp] = p;
    }
    __syncthreads();
    if (t == 0) out[gph] = red[0] + red[1] + red[2] + red[3] + b_fc[0];
}

extern "C" void kernel_launch(void* const* d_in, const int* in_sizes, int n_in,
                              void* d_out, int out_size) {
    const float* x       = (const float*)d_in[0];
    const int*   ei      = (const int*)d_in[1];
    const int*   batch   = (const int*)d_in[2];
    const float* W_gat   = (const float*)d_in[3];
    const float* att_src = (const float*)d_in[4];
    const float* att_dst = (const float*)d_in[5];
    const float* b_gat   = (const float*)d_in[6];
    const float* bn1_w   = (const float*)d_in[7];
    const float* bn1_b   = (const float*)d_in[8];
    const float* W_gcn   = (const float*)d_in[9];
    const float* b_gcn   = (const float*)d_in[10];
    const float* bn2_w   = (const float*)d_in[11];
    const float* bn2_b   = (const float*)d_in[12];
    const float* W_gate  = (const float*)d_in[13];
    const float* b_gate  = (const float*)d_in[14];
    const float* W_fc    = (const float*)d_in[15];
    const float* b_fc    = (const float*)d_in[16];
    float* out = (float*)d_out;

    int N = in_sizes[0] / 128;
    int E = in_sizes[1] / 2;
    if (N > NMAX) N = NMAX;
    if (E > EMAX) E = EMAX;

    float *p_h, *p_out1, *p_h2;
    cudaGetSymbolAddress((void**)&p_h, g_h);
    cudaGetSymbolAddress((void**)&p_out1, g_out1);
    cudaGetSymbolAddress((void**)&p_h2, g_h2);

    // CSR build
    k_prep<<<(N + 255) / 256, 256>>>(batch, N);
    k_count<<<(E + 255) / 256, 256>>>(ei, E);
    k_scan<<<1, 1024>>>(N);
    k_fill<<<(E + 255) / 256, 256>>>(ei, E);

    // GAT
    gemm128<<<(N + 127) / 128, 256>>>(x, W_gat, p_h, N);
    k_attn<<<(N * 4 + 255) / 256, 256>>>(att_src, att_dst, N);
    k_gat_agg<<<(N * 32 + 255) / 256, 256>>>(b_gat, bn1_w, bn1_b, N);

    // GCN
    gemm128<<<(N + 127) / 128, 256>>>(p_out1, W_gcn, p_h2, N);
    k_gcn_agg<<<(N * 32 + 255) / 256, 256>>>(b_gcn, bn2_w, bn2_b, W_gate, b_gate, N);

    // Pooling + FC
    k_pool_final<<<GSEG, 256>>>(W_fc, b_fc, out);
}